// round 7
// baseline (speedup 1.0000x reference)
#include <cuda_runtime.h>
#include <mma.h>
#include <math.h>

using namespace nvcuda;

#define BB 16
#define SS 784
#define DD 768
#define HH 12
#define DHH 64
#define M_TOT (BB*SS)

__device__ float g_q[BB*HH*SS*DHH];
__device__ float g_k[BB*HH*SS*DHH];
__device__ float g_v[BB*HH*SS*DHH];
__device__ float g_ctx[BB*SS*DD];
__device__ float g_hsr[M_TOT*DD];
__device__ float g_wr[4][DD*DD];

__device__ __forceinline__ void cpasync16(float* smem, const float* g){
    unsigned s = (unsigned)__cvta_generic_to_shared(smem);
    asm volatile("cp.async.cg.shared.global [%0], [%1], 16;\n" :: "r"(s), "l"(g));
}

// ---------------------------------------------------------------------------
// One-shot tf32 RN rounding of hs + 4 weight matrices
// ---------------------------------------------------------------------------
#define N4H ((M_TOT*DD)/4)
#define N4W ((DD*DD)/4)
__global__ void round_all_kernel(
    const float* __restrict__ hs, const float* __restrict__ w0,
    const float* __restrict__ w1, const float* __restrict__ w2,
    const float* __restrict__ w3,
    float* __restrict__ hsr, float* __restrict__ wr)
{
    int i = blockIdx.x*blockDim.x + threadIdx.x;
    const float4* src;
    float4* dst;
    if (i < N4H){
        src = (const float4*)hs; dst = (float4*)hsr;
    } else {
        int idx = i - N4H;
        int w = idx / N4W;
        i = idx - w*N4W;
        const float* ws[4] = {w0,w1,w2,w3};
        src = (const float4*)ws[w];
        dst = (float4*)(wr + (size_t)w*DD*DD);
    }
    float4 v = src[i];
    v.x = wmma::__float_to_tf32(v.x);
    v.y = wmma::__float_to_tf32(v.y);
    v.z = wmma::__float_to_tf32(v.z);
    v.w = wmma::__float_to_tf32(v.w);
    dst[i] = v;
}

// ---------------------------------------------------------------------------
// GEMM: 128x128 block, BK=32, 128 threads (4 warps, warp tile 64x64),
// 3-stage cp.async, one barrier/iter. LDS:HMMA ratio 1:1 (was 1.5:1).
// ---------------------------------------------------------------------------
#define GSTG 9216   // floats per stage (128*36 A + 128*36 B)

__global__ __launch_bounds__(128,2) void gemm_kernel(
    const float* __restrict__ A, const float* __restrict__ W,
    const float* __restrict__ bias, const float* __restrict__ rope,
    float* __restrict__ out, int mode, int do_rope)
{
    extern __shared__ float sm[];

    const int tid  = threadIdx.x;
    const int warp = tid >> 5;
    const int lane = tid & 31;
    const int wm   = warp >> 1;     // 0..1 (64 rows)
    const int wn   = warp & 1;      // 0..1 (64 cols)
    const int m0   = blockIdx.y * 128;
    const int n0   = blockIdx.x * 128;

    const int lrow = tid >> 3;           // 0..15
    const int lc4  = (tid & 7) * 4;

    wmma::fragment<wmma::accumulator,16,16,8,float> acc[4][4];
    #pragma unroll
    for (int i=0;i<4;i++)
        #pragma unroll
        for (int j=0;j<4;j++)
            wmma::fill_fragment(acc[i][j], 0.f);

    // prologue: stages 0,1
    #pragma unroll
    for (int s=0;s<2;s++){
        float* aS = sm + s*GSTG;
        float* bS = aS + 128*36;
        int k0 = s*32;
        #pragma unroll
        for (int i=0;i<8;i++){
            int row = lrow + i*16;
            cpasync16(aS + row*36 + lc4, A + (size_t)(m0+row)*768 + k0 + lc4);
            cpasync16(bS + row*36 + lc4, W + (size_t)(n0+row)*768 + k0 + lc4);
        }
        asm volatile("cp.async.commit_group;\n"::);
    }

    for (int it=0; it<24; ++it){
        if (it < 23) asm volatile("cp.async.wait_group 1;\n"::);
        else         asm volatile("cp.async.wait_group 0;\n"::);
        __syncthreads();

        if (it < 22){
            int s = (it+2)%3;
            float* aS = sm + s*GSTG;
            float* bS = aS + 128*36;
            int k0 = (it+2)*32;
            #pragma unroll
            for (int i=0;i<8;i++){
                int row = lrow + i*16;
                cpasync16(aS + row*36 + lc4, A + (size_t)(m0+row)*768 + k0 + lc4);
                cpasync16(bS + row*36 + lc4, W + (size_t)(n0+row)*768 + k0 + lc4);
            }
            asm volatile("cp.async.commit_group;\n"::);
        }

        float* aS = sm + (it%3)*GSTG;
        float* bS = aS + 128*36;
        #pragma unroll
        for (int kk=0;kk<4;kk++){
            wmma::fragment<wmma::matrix_a,16,16,8,wmma::precision::tf32,wmma::row_major> af[4];
            wmma::fragment<wmma::matrix_b,16,16,8,wmma::precision::tf32,wmma::col_major> bf[4];
            #pragma unroll
            for (int i=0;i<4;i++)
                wmma::load_matrix_sync(af[i], aS + (wm*64 + i*16)*36 + kk*8, 36);
            #pragma unroll
            for (int j=0;j<4;j++)
                wmma::load_matrix_sync(bf[j], bS + (wn*64 + j*16)*36 + kk*8, 36);
            #pragma unroll
            for (int i=0;i<4;i++)
                #pragma unroll
                for (int j=0;j<4;j++)
                    wmma::mma_sync(acc[i][j], af[i], bf[j], acc[i][j]);
        }
    }
    __syncthreads();

    // epilogue: per-warp staging
    float* ws = sm + warp * (16*20);
    #pragma unroll
    for (int i=0;i<4;i++){
        #pragma unroll
        for (int j=0;j<4;j++){
            wmma::store_matrix_sync(ws, acc[i][j], 20, wmma::mem_row_major);
            __syncwarp();
            int row  = lane >> 1;
            int cbase = (lane & 1) * 8;
            int m = m0 + wm*64 + i*16 + row;
            int nbase = n0 + wn*64 + j*16 + cbase;
            if (mode == 1){
                #pragma unroll
                for (int cc=0;cc<8;cc++){
                    int n = nbase + cc;
                    out[(size_t)m*768 + n] = ws[row*20 + cbase + cc] + bias[n];
                }
            } else {
                int b = m / SS, s = m % SS;
                #pragma unroll
                for (int p=0;p<4;p++){
                    int n = nbase + p*2;
                    int h = n >> 6, col = n & 63;
                    float v0 = ws[row*20 + cbase + p*2]     + bias[n];
                    float v1 = ws[row*20 + cbase + p*2 + 1] + bias[n+1];
                    if (do_rope){
                        float t0 = rope[(size_t)(b*SS + s)*DHH + col];
                        float t1 = rope[(size_t)(b*SS + s)*DHH + col + 1];
                        float c0, s0, c1, s1;
                        sincosf(t0, &s0, &c0);
                        sincosf(t1, &s1, &c1);
                        float o0 = v0*c0 - v1*s0;
                        float o1 = v1*c1 + v0*s1;
                        v0 = o0; v1 = o1;
                    }
                    float* dst = out + (((size_t)(b*HH + h)*SS) + s)*DHH + col;
                    dst[0] = wmma::__float_to_tf32(v0);
                    dst[1] = wmma::__float_to_tf32(v1);
                }
            }
            __syncwarp();
        }
    }
}

// ---------------------------------------------------------------------------
// Attention — best-known configuration (256 threads, 8 warps: 4 wm x 2 wn).
// ---------------------------------------------------------------------------
#define QT 64
#define KT 112
#define NKT 7
#define KVLD 68

__global__ __launch_bounds__(256) void attn_kernel()
{
    extern __shared__ float sm[];
    float* scores = sm;                 // 64 x 784
    float* kv     = sm + QT*SS;         // 112 x 68

    const int tid  = threadIdx.x;
    const int warp = tid >> 5;
    const int wm   = warp >> 1;
    const int wn   = warp & 1;
    const int q0   = blockIdx.x * QT;
    const int h    = blockIdx.y;
    const int b    = blockIdx.z;
    const float scale = 0.125f;
    const size_t base = ((size_t)(b*HH + h)) * SS * DHH;

    const int prow = tid >> 4;
    const int pc4  = (tid & 15) * 4;

    #pragma unroll
    for (int i=0;i<4;i++){
        int lin = tid + i*256;
        int row = lin >> 4, c4 = (lin & 15) * 4;
        int s = q0 + row;
        float4 v = make_float4(0.f,0.f,0.f,0.f);
        if (s < SS) v = *(const float4*)(g_q + base + (size_t)s*DHH + c4);
        v.x *= scale; v.y *= scale; v.z *= scale; v.w *= scale;
        *(float4*)(kv + row*KVLD + c4) = v;
    }
    __syncthreads();

    wmma::fragment<wmma::matrix_a,16,16,8,wmma::precision::tf32,wmma::row_major> qf[8];
    #pragma unroll
    for (int kk=0;kk<8;kk++)
        wmma::load_matrix_sync(qf[kk], kv + (wm*16)*KVLD + kk*8, KVLD);

    float4 pre[7];
    #pragma unroll
    for (int i=0;i<7;i++)
        pre[i] = *(const float4*)(g_k + base + (size_t)(prow + i*16)*DHH + pc4);

    const int j_lo = wn ? 4 : 0;
    const int j_hi = wn ? 7 : 4;
    for (int t=0;t<NKT;t++){
        __syncthreads();
        #pragma unroll
        for (int i=0;i<7;i++)
            *(float4*)(kv + (prow + i*16)*KVLD + pc4) = pre[i];
        __syncthreads();
        if (t < NKT-1){
            #pragma unroll
            for (int i=0;i<7;i++)
                pre[i] = *(const float4*)(g_k + base + (size_t)((t+1)*KT + prow + i*16)*DHH + pc4);
        }

        for (int j=j_lo; j<j_hi; j+=2){
            bool two = (j+1 < j_hi);
            wmma::fragment<wmma::accumulator,16,16,8,float> sc0, sc1;
            wmma::fill_fragment(sc0, 0.f);
            wmma::fill_fragment(sc1, 0.f);
            #pragma unroll
            for (int kk=0;kk<8;kk++){
                wmma::fragment<wmma::matrix_b,16,16,8,wmma::precision::tf32,wmma::col_major> bf0, bf1;
                wmma::load_matrix_sync(bf0, kv + (j*16)*KVLD + kk*8, KVLD);
                if (two) wmma::load_matrix_sync(bf1, kv + ((j+1)*16)*KVLD + kk*8, KVLD);
                wmma::mma_sync(sc0, qf[kk], bf0, sc0);
                if (two) wmma::mma_sync(sc1, qf[kk], bf1, sc1);
            }
            wmma::store_matrix_sync(scores + (wm*16)*SS + t*KT + j*16, sc0, SS, wmma::mem_row_major);
            if (two)
                wmma::store_matrix_sync(scores + (wm*16)*SS + t*KT + (j+1)*16, sc1, SS, wmma::mem_row_major);
        }
    }
    __syncthreads();

    {
        int r = tid >> 2, quad = tid & 3;
        float* p = scores + (size_t)r*SS;
        int c0 = quad * 196, c1 = c0 + 196;
        float mx = -1e30f;
        for (int c=c0;c<c1;c++) mx = fmaxf(mx, p[c]);
        mx = fmaxf(mx, __shfl_xor_sync(0xffffffffu, mx, 1));
        mx = fmaxf(mx, __shfl_xor_sync(0xffffffffu, mx, 2));
        float sum = 0.f;
        for (int c=c0;c<c1;c++){ float e = __expf(p[c] - mx); p[c] = e; sum += e; }
        sum += __shfl_xor_sync(0xffffffffu, sum, 1);
        sum += __shfl_xor_sync(0xffffffffu, sum, 2);
        float inv = 1.f / sum;
        for (int c=c0;c<c1;c++) p[c] = wmma::__float_to_tf32(p[c] * inv);
    }

    #pragma unroll
    for (int i=0;i<7;i++)
        pre[i] = *(const float4*)(g_v + base + (size_t)(prow + i*16)*DHH + pc4);

    wmma::fragment<wmma::accumulator,16,16,8,float> oacc[2][2];
    #pragma unroll
    for (int j=0;j<2;j++)
        #pragma unroll
        for (int p=0;p<2;p++)
            wmma::fill_fragment(oacc[j][p], 0.f);

    for (int t=0;t<NKT;t++){
        __syncthreads();
        #pragma unroll
        for (int i=0;i<7;i++)
            *(float4*)(kv + (prow + i*16)*KVLD + pc4) = pre[i];
        __syncthreads();
        if (t < NKT-1){
            #pragma unroll
            for (int i=0;i<7;i++)
                pre[i] = *(const float4*)(g_v + base + (size_t)((t+1)*KT + prow + i*16)*DHH + pc4);
        }

        #pragma unroll
        for (int kk=0;kk<14;kk++){
            int par = kk & 1;
            wmma::fragment<wmma::matrix_a,16,16,8,wmma::precision::tf32,wmma::row_major> pf;
            wmma::load_matrix_sync(pf, scores + (wm*16)*SS + t*KT + kk*8, SS);
            #pragma unroll
            for (int j=0;j<2;j++){
                wmma::fragment<wmma::matrix_b,16,16,8,wmma::precision::tf32,wmma::row_major> bf;
                wmma::load_matrix_sync(bf, kv + (kk*8)*KVLD + wn*32 + j*16, KVLD);
                wmma::mma_sync(oacc[j][par], pf, bf, oacc[j][par]);
            }
        }
    }

    #pragma unroll
    for (int j=0;j<2;j++)
        #pragma unroll
        for (int u=0;u<oacc[j][0].num_elements;u++)
            oacc[j][0].x[u] += oacc[j][1].x[u];

    __syncthreads();
    #pragma unroll
    for (int j=0;j<2;j++)
        wmma::store_matrix_sync(kv + (wm*16)*KVLD + wn*32 + j*16, oacc[j][0], KVLD, wmma::mem_row_major);
    __syncthreads();
    #pragma unroll
    for (int i=0;i<16;i++){
        int lin = tid + i*256;
        int row = lin >> 6, col = lin & 63;
        int s = q0 + row;
        if (s < SS)
            g_ctx[((size_t)b*SS + s)*DD + h*DHH + col] = wmma::__float_to_tf32(kv[row*KVLD + col]);
    }
}

// ---------------------------------------------------------------------------
extern "C" void kernel_launch(void* const* d_in, const int* in_sizes, int n_in,
                              void* d_out, int out_size)
{
    const float* hs   = (const float*)d_in[0];
    const float* rope = (const float*)d_in[1];
    const float* wq   = (const float*)d_in[2];
    const float* bq   = (const float*)d_in[3];
    const float* wk   = (const float*)d_in[4];
    const float* bk   = (const float*)d_in[5];
    const float* wv   = (const float*)d_in[6];
    const float* bv   = (const float*)d_in[7];
    const float* wo   = (const float*)d_in[8];
    const float* bo   = (const float*)d_in[9];
    float* out = (float*)d_out;

    float *q, *k, *v, *ctx, *hsr, *wr;
    cudaGetSymbolAddress((void**)&q,   g_q);
    cudaGetSymbolAddress((void**)&k,   g_k);
    cudaGetSymbolAddress((void**)&v,   g_v);
    cudaGetSymbolAddress((void**)&ctx, g_ctx);
    cudaGetSymbolAddress((void**)&hsr, g_hsr);
    cudaGetSymbolAddress((void**)&wr,  g_wr);

    const size_t gemm_smem = 3 * GSTG * sizeof(float);        // 110,592 B
    const size_t attn_smem = (QT*SS + KT*KVLD)*sizeof(float); // 231,168 B

    cudaFuncSetAttribute(gemm_kernel, cudaFuncAttributeMaxDynamicSharedMemorySize, (int)gemm_smem);
    cudaFuncSetAttribute(attn_kernel, cudaFuncAttributeMaxDynamicSharedMemorySize, (int)attn_smem);

    {
        int n4 = N4H + 4*N4W;
        round_all_kernel<<<(n4+255)/256, 256>>>(hs, wq, wk, wv, wo, hsr, wr);
    }

    dim3 ggrid(6, 98);
    gemm_kernel<<<ggrid, 128, gemm_smem>>>(hsr, wr,            bq, rope, q, 0, 1);
    gemm_kernel<<<ggrid, 128, gemm_smem>>>(hsr, wr +   DD*DD,  bk, rope, k, 0, 1);
    gemm_kernel<<<ggrid, 128, gemm_smem>>>(hsr, wr + 2*DD*DD,  bv, rope, v, 0, 0);

    attn_kernel<<<dim3(13, HH, BB), 256, attn_smem>>>();

    gemm_kernel<<<ggrid, 128, gemm_smem>>>(ctx, wr + 3*DD*DD,  bo, nullptr, out, 1, 0);
}

// round 8
// speedup vs baseline: 1.3716x; 1.3716x over previous
#include <cuda_runtime.h>
#include <mma.h>
#include <math.h>

using namespace nvcuda;

#define BB 16
#define SS 784
#define DD 768
#define HH 12
#define DHH 64
#define M_TOT (BB*SS)

__device__ float g_q[BB*HH*SS*DHH];
__device__ float g_k[BB*HH*SS*DHH];
__device__ float g_v[BB*HH*SS*DHH];
__device__ float g_ctx[BB*SS*DD];
__device__ float g_hsr[M_TOT*DD];
__device__ float g_wr[4][DD*DD];

__device__ __forceinline__ void cpasync16(float* smem, const float* g){
    unsigned s = (unsigned)__cvta_generic_to_shared(smem);
    asm volatile("cp.async.cg.shared.global [%0], [%1], 16;\n" :: "r"(s), "l"(g));
}

__device__ __forceinline__ void mma_tf32(float* d, const float* a, float b0, float b1){
    asm volatile("mma.sync.aligned.m16n8k8.row.col.f32.tf32.tf32.f32 "
        "{%0,%1,%2,%3}, {%4,%5,%6,%7}, {%8,%9}, {%0,%1,%2,%3};"
        : "+f"(d[0]), "+f"(d[1]), "+f"(d[2]), "+f"(d[3])
        : "f"(a[0]), "f"(a[1]), "f"(a[2]), "f"(a[3]), "f"(b0), "f"(b1));
}

// ---------------------------------------------------------------------------
// One-shot tf32 RN rounding of hs + 4 weight matrices
// ---------------------------------------------------------------------------
#define N4H ((M_TOT*DD)/4)
#define N4W ((DD*DD)/4)
__global__ void round_all_kernel(
    const float* __restrict__ hs, const float* __restrict__ w0,
    const float* __restrict__ w1, const float* __restrict__ w2,
    const float* __restrict__ w3,
    float* __restrict__ hsr, float* __restrict__ wr)
{
    int i = blockIdx.x*blockDim.x + threadIdx.x;
    const float4* src;
    float4* dst;
    if (i < N4H){
        src = (const float4*)hs; dst = (float4*)hsr;
    } else {
        int idx = i - N4H;
        int w = idx / N4W;
        i = idx - w*N4W;
        const float* ws[4] = {w0,w1,w2,w3};
        src = (const float4*)ws[w];
        dst = (float4*)(wr + (size_t)w*DD*DD);
    }
    float4 v = src[i];
    v.x = wmma::__float_to_tf32(v.x);
    v.y = wmma::__float_to_tf32(v.y);
    v.z = wmma::__float_to_tf32(v.z);
    v.w = wmma::__float_to_tf32(v.w);
    dst[i] = v;
}

// ---------------------------------------------------------------------------
// GEMM (R7): 128x128 block, BK=32, 128 threads (4 warps, warp tile 64x64),
// 3-stage cp.async, one barrier/iter.
// ---------------------------------------------------------------------------
#define GSTG 9216

__global__ __launch_bounds__(128,2) void gemm_kernel(
    const float* __restrict__ A, const float* __restrict__ W,
    const float* __restrict__ bias, const float* __restrict__ rope,
    float* __restrict__ out, int mode, int do_rope)
{
    extern __shared__ float sm[];

    const int tid  = threadIdx.x;
    const int warp = tid >> 5;
    const int lane = tid & 31;
    const int wm   = warp >> 1;
    const int wn   = warp & 1;
    const int m0   = blockIdx.y * 128;
    const int n0   = blockIdx.x * 128;

    const int lrow = tid >> 3;
    const int lc4  = (tid & 7) * 4;

    wmma::fragment<wmma::accumulator,16,16,8,float> acc[4][4];
    #pragma unroll
    for (int i=0;i<4;i++)
        #pragma unroll
        for (int j=0;j<4;j++)
            wmma::fill_fragment(acc[i][j], 0.f);

    #pragma unroll
    for (int s=0;s<2;s++){
        float* aS = sm + s*GSTG;
        float* bS = aS + 128*36;
        int k0 = s*32;
        #pragma unroll
        for (int i=0;i<8;i++){
            int row = lrow + i*16;
            cpasync16(aS + row*36 + lc4, A + (size_t)(m0+row)*768 + k0 + lc4);
            cpasync16(bS + row*36 + lc4, W + (size_t)(n0+row)*768 + k0 + lc4);
        }
        asm volatile("cp.async.commit_group;\n"::);
    }

    for (int it=0; it<24; ++it){
        if (it < 23) asm volatile("cp.async.wait_group 1;\n"::);
        else         asm volatile("cp.async.wait_group 0;\n"::);
        __syncthreads();

        if (it < 22){
            int s = (it+2)%3;
            float* aS = sm + s*GSTG;
            float* bS = aS + 128*36;
            int k0 = (it+2)*32;
            #pragma unroll
            for (int i=0;i<8;i++){
                int row = lrow + i*16;
                cpasync16(aS + row*36 + lc4, A + (size_t)(m0+row)*768 + k0 + lc4);
                cpasync16(bS + row*36 + lc4, W + (size_t)(n0+row)*768 + k0 + lc4);
            }
            asm volatile("cp.async.commit_group;\n"::);
        }

        float* aS = sm + (it%3)*GSTG;
        float* bS = aS + 128*36;
        #pragma unroll
        for (int kk=0;kk<4;kk++){
            wmma::fragment<wmma::matrix_a,16,16,8,wmma::precision::tf32,wmma::row_major> af[4];
            wmma::fragment<wmma::matrix_b,16,16,8,wmma::precision::tf32,wmma::col_major> bf[4];
            #pragma unroll
            for (int i=0;i<4;i++)
                wmma::load_matrix_sync(af[i], aS + (wm*64 + i*16)*36 + kk*8, 36);
            #pragma unroll
            for (int j=0;j<4;j++)
                wmma::load_matrix_sync(bf[j], bS + (wn*64 + j*16)*36 + kk*8, 36);
            #pragma unroll
            for (int i=0;i<4;i++)
                #pragma unroll
                for (int j=0;j<4;j++)
                    wmma::mma_sync(acc[i][j], af[i], bf[j], acc[i][j]);
        }
    }
    __syncthreads();

    float* ws = sm + warp * (16*20);
    #pragma unroll
    for (int i=0;i<4;i++){
        #pragma unroll
        for (int j=0;j<4;j++){
            wmma::store_matrix_sync(ws, acc[i][j], 20, wmma::mem_row_major);
            __syncwarp();
            int row  = lane >> 1;
            int cbase = (lane & 1) * 8;
            int m = m0 + wm*64 + i*16 + row;
            int nbase = n0 + wn*64 + j*16 + cbase;
            if (mode == 1){
                #pragma unroll
                for (int cc=0;cc<8;cc++){
                    int n = nbase + cc;
                    out[(size_t)m*768 + n] = ws[row*20 + cbase + cc] + bias[n];
                }
            } else {
                int b = m / SS, s = m % SS;
                #pragma unroll
                for (int p=0;p<4;p++){
                    int n = nbase + p*2;
                    int h = n >> 6, col = n & 63;
                    float v0 = ws[row*20 + cbase + p*2]     + bias[n];
                    float v1 = ws[row*20 + cbase + p*2 + 1] + bias[n+1];
                    if (do_rope){
                        float t0 = rope[(size_t)(b*SS + s)*DHH + col];
                        float t1 = rope[(size_t)(b*SS + s)*DHH + col + 1];
                        float c0, s0, c1, s1;
                        sincosf(t0, &s0, &c0);
                        sincosf(t1, &s1, &c1);
                        float o0 = v0*c0 - v1*s0;
                        float o1 = v1*c1 + v0*s1;
                        v0 = o0; v1 = o1;
                    }
                    float* dst = out + (((size_t)(b*HH + h)*SS) + s)*DHH + col;
                    dst[0] = wmma::__float_to_tf32(v0);
                    dst[1] = wmma::__float_to_tf32(v1);
                }
            }
            __syncwarp();
        }
    }
}

// ---------------------------------------------------------------------------
// Flash attention: QT=128, 256 threads, 8 warps each owning 16 full q-rows.
// S tile (16x56/warp) register-resident (raw mma m16n8k8 tf32).
// Online softmax fully in registers. 3 rotating K/V smem buffers (cp.async).
// ---------------------------------------------------------------------------
#define QTA 128
#define KTA 56
#define NTA 14
#define KLD 68

__global__ __launch_bounds__(256,2) void attn_kernel()
{
    extern __shared__ float sm[];   // 3 buffers of [KTA][KLD]

    const int tid  = threadIdx.x;
    const int warp = tid >> 5;
    const int lane = tid & 31;
    const int g    = lane >> 2;     // 0..7
    const int c    = lane & 3;      // 0..3
    const int q0   = blockIdx.x * QTA;
    const int h    = blockIdx.y;
    const int b    = blockIdx.z;
    const size_t base = ((size_t)(b*HH + h)) * SS * DHH;

    // ---- stage q tile (scaled by 0.125) into smem, load A-frags ----
    #pragma unroll
    for (int i=0;i<8;i++){
        int lin = tid + i*256;
        int row = lin >> 4, c4 = (lin & 15)*4;
        int s = q0 + row;
        float4 v = make_float4(0.f,0.f,0.f,0.f);
        if (s < SS) v = *(const float4*)(g_q + base + (size_t)s*DHH + c4);
        v.x *= 0.125f; v.y *= 0.125f; v.z *= 0.125f; v.w *= 0.125f;
        *(float4*)(sm + row*KLD + c4) = v;
    }
    __syncthreads();

    float qa[8][4];
    {
        const float* qr = sm + (warp*16)*KLD;
        #pragma unroll
        for (int kk=0;kk<8;kk++){
            qa[kk][0] = qr[(g  )*KLD + kk*8 + c];
            qa[kk][1] = qr[(g+8)*KLD + kk*8 + c];
            qa[kk][2] = qr[(g  )*KLD + kk*8 + c + 4];
            qa[kk][3] = qr[(g+8)*KLD + kk*8 + c + 4];
        }
    }
    __syncthreads();

    // ---- pipeline: load i (even=K_{i/2}, odd=V_{i/2}) into buffer i%3 ----
    #define ISSUE_LOAD(i_) do { \
        const float* _src = ((i_) & 1) ? g_v : g_k; \
        int _tile = (i_) >> 1; \
        float* _dst = sm + ((i_) % 3)*KTA*KLD; \
        _Pragma("unroll") \
        for (int _p=0;_p<4;_p++){ \
            int _lin = tid + _p*256; \
            int _row = _lin >> 4, _c4 = (_lin & 15)*4; \
            if (_row < KTA) \
                cpasync16(_dst + _row*KLD + _c4, _src + base + (size_t)(_tile*KTA + _row)*DHH + _c4); \
        } \
        asm volatile("cp.async.commit_group;\n"::); \
    } while(0)

    ISSUE_LOAD(0); ISSUE_LOAD(1); ISSUE_LOAD(2);

    float o[8][4];
    #pragma unroll
    for (int j=0;j<8;j++){ o[j][0]=o[j][1]=o[j][2]=o[j][3]=0.f; }
    float m0r = -1e30f, m1r = -1e30f, l0 = 0.f, l1 = 0.f;

    for (int t=0; t<NTA; ++t){
        if (t < NTA-1) asm volatile("cp.async.wait_group 1;\n"::);
        else           asm volatile("cp.async.wait_group 0;\n"::);
        __syncthreads();            // K_t and V_t visible to all
        const float* Ksm = sm + ((2*t  )%3)*KTA*KLD;
        const float* Vsm = sm + ((2*t+1)%3)*KTA*KLD;

        // ---- S = q @ k^T : 7 independent 16x8 accs ----
        float sc[7][4];
        #pragma unroll
        for (int j=0;j<7;j++){ sc[j][0]=sc[j][1]=sc[j][2]=sc[j][3]=0.f; }
        #pragma unroll
        for (int kk=0;kk<8;kk++){
            #pragma unroll
            for (int j=0;j<7;j++){
                float b0 = Ksm[(j*8 + g)*KLD + kk*8 + c];
                float b1 = Ksm[(j*8 + g)*KLD + kk*8 + c + 4];
                mma_tf32(sc[j], qa[kk], b0, b1);
            }
        }

        // ---- online softmax (registers only) ----
        float tm0 = -1e30f, tm1 = -1e30f;
        #pragma unroll
        for (int j=0;j<7;j++){
            tm0 = fmaxf(tm0, fmaxf(sc[j][0], sc[j][1]));
            tm1 = fmaxf(tm1, fmaxf(sc[j][2], sc[j][3]));
        }
        tm0 = fmaxf(tm0, __shfl_xor_sync(0xffffffffu, tm0, 1));
        tm0 = fmaxf(tm0, __shfl_xor_sync(0xffffffffu, tm0, 2));
        tm1 = fmaxf(tm1, __shfl_xor_sync(0xffffffffu, tm1, 1));
        tm1 = fmaxf(tm1, __shfl_xor_sync(0xffffffffu, tm1, 2));
        float nm0 = fmaxf(m0r, tm0), nm1 = fmaxf(m1r, tm1);
        float f0 = __expf(m0r - nm0), f1 = __expf(m1r - nm1);
        m0r = nm0; m1r = nm1;
        float s0 = 0.f, s1 = 0.f;
        #pragma unroll
        for (int j=0;j<7;j++){
            sc[j][0] = __expf(sc[j][0] - nm0); s0 += sc[j][0];
            sc[j][1] = __expf(sc[j][1] - nm0); s0 += sc[j][1];
            sc[j][2] = __expf(sc[j][2] - nm1); s1 += sc[j][2];
            sc[j][3] = __expf(sc[j][3] - nm1); s1 += sc[j][3];
        }
        s0 += __shfl_xor_sync(0xffffffffu, s0, 1);
        s0 += __shfl_xor_sync(0xffffffffu, s0, 2);
        s1 += __shfl_xor_sync(0xffffffffu, s1, 1);
        s1 += __shfl_xor_sync(0xffffffffu, s1, 2);
        l0 = l0*f0 + s0; l1 = l1*f1 + s1;
        #pragma unroll
        for (int j=0;j<8;j++){
            o[j][0] *= f0; o[j][1] *= f0; o[j][2] *= f1; o[j][3] *= f1;
        }

        // ---- PV: transpose P c-frag -> a-frag via shfl, mma into O ----
        const int lsrc  = (lane & ~3) | (c >> 1);
        const int lsrc2 = lsrc + 2;
        #pragma unroll
        for (int kc=0;kc<7;kc++){
            float pa[4];
            {
                float v0 = __shfl_sync(0xffffffffu, sc[kc][0], lsrc);
                float v1 = __shfl_sync(0xffffffffu, sc[kc][1], lsrc);
                float w0 = __shfl_sync(0xffffffffu, sc[kc][0], lsrc2);
                float w1 = __shfl_sync(0xffffffffu, sc[kc][1], lsrc2);
                float x0 = __shfl_sync(0xffffffffu, sc[kc][2], lsrc);
                float x1 = __shfl_sync(0xffffffffu, sc[kc][3], lsrc);
                float y0 = __shfl_sync(0xffffffffu, sc[kc][2], lsrc2);
                float y1 = __shfl_sync(0xffffffffu, sc[kc][3], lsrc2);
                pa[0] = wmma::__float_to_tf32((c & 1) ? v1 : v0);
                pa[2] = wmma::__float_to_tf32((c & 1) ? w1 : w0);
                pa[1] = wmma::__float_to_tf32((c & 1) ? x1 : x0);
                pa[3] = wmma::__float_to_tf32((c & 1) ? y1 : y0);
            }
            #pragma unroll
            for (int j=0;j<8;j++){
                float b0 = Vsm[(kc*8 + c    )*KLD + j*8 + g];
                float b1 = Vsm[(kc*8 + c + 4)*KLD + j*8 + g];
                mma_tf32(o[j], pa, b0, b1);
            }
        }

        __syncthreads();            // buffers (2t)%3, (2t+1)%3 free
        if (t+1 < NTA) ISSUE_LOAD(2*t+3);   // V_{t+1} -> buf (2t)%3
        if (t+2 < NTA) ISSUE_LOAD(2*t+4);   // K_{t+2} -> buf (2t+1)%3
    }

    // ---- normalize + store ctx (tf32-rounded: feeds final GEMM) ----
    float inv0 = 1.f / l0, inv1 = 1.f / l1;
    int r0 = q0 + warp*16 + g;
    int r1 = r0 + 8;
    #pragma unroll
    for (int j=0;j<8;j++){
        if (r0 < SS){
            float2 v;
            v.x = wmma::__float_to_tf32(o[j][0]*inv0);
            v.y = wmma::__float_to_tf32(o[j][1]*inv0);
            *(float2*)(g_ctx + ((size_t)b*SS + r0)*DD + h*DHH + j*8 + 2*c) = v;
        }
        if (r1 < SS){
            float2 v;
            v.x = wmma::__float_to_tf32(o[j][2]*inv1);
            v.y = wmma::__float_to_tf32(o[j][3]*inv1);
            *(float2*)(g_ctx + ((size_t)b*SS + r1)*DD + h*DHH + j*8 + 2*c) = v;
        }
    }
    #undef ISSUE_LOAD
}

// ---------------------------------------------------------------------------
extern "C" void kernel_launch(void* const* d_in, const int* in_sizes, int n_in,
                              void* d_out, int out_size)
{
    const float* hs   = (const float*)d_in[0];
    const float* rope = (const float*)d_in[1];
    const float* wq   = (const float*)d_in[2];
    const float* bq   = (const float*)d_in[3];
    const float* wk   = (const float*)d_in[4];
    const float* bk   = (const float*)d_in[5];
    const float* wv   = (const float*)d_in[6];
    const float* bv   = (const float*)d_in[7];
    const float* wo   = (const float*)d_in[8];
    const float* bo   = (const float*)d_in[9];
    float* out = (float*)d_out;

    float *q, *k, *v, *ctx, *hsr, *wr;
    cudaGetSymbolAddress((void**)&q,   g_q);
    cudaGetSymbolAddress((void**)&k,   g_k);
    cudaGetSymbolAddress((void**)&v,   g_v);
    cudaGetSymbolAddress((void**)&ctx, g_ctx);
    cudaGetSymbolAddress((void**)&hsr, g_hsr);
    cudaGetSymbolAddress((void**)&wr,  g_wr);

    const size_t gemm_smem = 3 * GSTG * sizeof(float);          // 110,592 B
    const size_t attn_smem = 3 * KTA * KLD * sizeof(float);     // 45,696 B

    cudaFuncSetAttribute(gemm_kernel, cudaFuncAttributeMaxDynamicSharedMemorySize, (int)gemm_smem);

    {
        int n4 = N4H + 4*N4W;
        round_all_kernel<<<(n4+255)/256, 256>>>(hs, wq, wk, wv, wo, hsr, wr);
    }

    dim3 ggrid(6, 98);
    gemm_kernel<<<ggrid, 128, gemm_smem>>>(hsr, wr,            bq, rope, q, 0, 1);
    gemm_kernel<<<ggrid, 128, gemm_smem>>>(hsr, wr +   DD*DD,  bk, rope, k, 0, 1);
    gemm_kernel<<<ggrid, 128, gemm_smem>>>(hsr, wr + 2*DD*DD,  bv, rope, v, 0, 0);

    attn_kernel<<<dim3(7, HH, BB), 256, attn_smem>>>();

    gemm_kernel<<<ggrid, 128, gemm_smem>>>(ctx, wr + 3*DD*DD,  bo, nullptr, out, 1, 0);
}